// round 1
// baseline (speedup 1.0000x reference)
#include <cuda_runtime.h>
#include <math.h>

// Problem constants
#define B_  8
#define L_  256
#define DM_ 1024
#define DI_ 2048
#define N_  16
#define K_  4
#define NL_ 4
#define DTR_ 128
#define P_  97
#define M_TOK (B_*L_)          // 2048 token rows
#define XPW_ (DTR_ + 2*N_)     // 160

// ---------------- scratch (static device globals; no allocation) ----------------
__device__ float g_h [M_TOK*DM_];       // residual stream
__device__ float g_x [M_TOK*DM_];       // layernorm output
__device__ float g_xz[M_TOK*2*DI_];     // in_proj output (x | z)
__device__ float g_xb[M_TOK*DI_];       // conv+silu branch
__device__ float g_xp[M_TOK*XPW_];      // xproj output (dt_r | B | C)
__device__ float g_dl[M_TOK*DI_];       // delta (softplus)
__device__ float g_y [M_TOK*DI_];       // gated ssm output
__device__ float g_fin[B_*DM_];         // final LN of last tokens

// ---------------- embedding ----------------
__global__ void embed_k(const int* __restrict__ tok, const float* __restrict__ te,
                        const float* __restrict__ pe, float* __restrict__ h) {
    int row = blockIdx.x;              // b*L + l
    int l = row & (L_ - 1);
    int t = tok[row];
    const float* tsrc = te + (long)t * DM_;
    const float* psrc = pe + (long)l * DM_;
    float* dst = h + (long)row * DM_;
    for (int d = threadIdx.x; d < DM_; d += 256)
        dst[d] = tsrc[d] + psrc[d];
}

// ---------------- layernorm (row of 1024, 256 threads x 4) ----------------
__global__ void ln_k(const float* __restrict__ in, long istride,
                     float* __restrict__ out, long ostride,
                     const float* __restrict__ w, const float* __restrict__ bb) {
    __shared__ float red[8];
    __shared__ float s_mean, s_rstd;
    int t = threadIdx.x;
    int row = blockIdx.x;
    const float* src = in + (long)row * istride;
    float v[4];
    float s = 0.f;
#pragma unroll
    for (int i = 0; i < 4; i++) { v[i] = src[t + i*256]; s += v[i]; }
#pragma unroll
    for (int o = 16; o; o >>= 1) s += __shfl_xor_sync(~0u, s, o);
    if ((t & 31) == 0) red[t >> 5] = s;
    __syncthreads();
    if (t < 32) {
        float x = (t < 8) ? red[t] : 0.f;
#pragma unroll
        for (int o = 4; o; o >>= 1) x += __shfl_xor_sync(~0u, x, o);
        if (t == 0) s_mean = x * (1.f/DM_);
    }
    __syncthreads();
    float mean = s_mean;
    float q = 0.f;
#pragma unroll
    for (int i = 0; i < 4; i++) { float d = v[i] - mean; q += d * d; }
#pragma unroll
    for (int o = 16; o; o >>= 1) q += __shfl_xor_sync(~0u, q, o);
    if ((t & 31) == 0) red[t >> 5] = q;
    __syncthreads();
    if (t < 32) {
        float x = (t < 8) ? red[t] : 0.f;
#pragma unroll
        for (int o = 4; o; o >>= 1) x += __shfl_xor_sync(~0u, x, o);
        if (t == 0) s_rstd = rsqrtf(x * (1.f/DM_) + 1e-5f);
    }
    __syncthreads();
    float r = s_rstd;
    float* dst = out + (long)row * ostride;
#pragma unroll
    for (int i = 0; i < 4; i++) {
        int idx = t + i*256;
        dst[idx] = (v[i] - mean) * r * w[idx] + bb[idx];
    }
}

// ---------------- generic SGEMM: C[m,n] = sum_k A[m,k]*W[n,k] (+bias +add, act) ----------------
// 128x128x8 tile, 256 threads, 8x8 microtile. act: 0=none, 1=softplus
__global__ __launch_bounds__(256)
void sgemm_nt(int M, int N, int Kd,
              const float* __restrict__ A, int lda,
              const float* __restrict__ W, int ldb,
              float* __restrict__ C, int ldc,
              const float* __restrict__ bias,
              const float* __restrict__ add, int ldadd,
              int act) {
    __shared__ float As[8][128];
    __shared__ float Bs[8][128];
    int tid = threadIdx.x;
    int tr = tid >> 4, tc = tid & 15;
    int aRow = tid >> 1;
    int aCol = (tid & 1) * 4;
    int gARow = blockIdx.y * 128 + aRow;
    int gBRow = blockIdx.x * 128 + aRow;
    bool aOK = gARow < M;
    bool bOK = gBRow < N;
    const float* Abase = A + (long)gARow * lda + aCol;
    const float* Wbase = W + (long)gBRow * ldb + aCol;

    float acc[8][8];
#pragma unroll
    for (int i = 0; i < 8; i++)
#pragma unroll
        for (int j = 0; j < 8; j++) acc[i][j] = 0.f;

    for (int k0 = 0; k0 < Kd; k0 += 8) {
        float4 av = aOK ? *reinterpret_cast<const float4*>(Abase + k0) : make_float4(0,0,0,0);
        float4 bv = bOK ? *reinterpret_cast<const float4*>(Wbase + k0) : make_float4(0,0,0,0);
        As[aCol+0][aRow] = av.x; As[aCol+1][aRow] = av.y;
        As[aCol+2][aRow] = av.z; As[aCol+3][aRow] = av.w;
        Bs[aCol+0][aRow] = bv.x; Bs[aCol+1][aRow] = bv.y;
        Bs[aCol+2][aRow] = bv.z; Bs[aCol+3][aRow] = bv.w;
        __syncthreads();
#pragma unroll
        for (int k = 0; k < 8; k++) {
            float ar[8], br[8];
#pragma unroll
            for (int i = 0; i < 8; i++) ar[i] = As[k][tr*8 + i];
#pragma unroll
            for (int j = 0; j < 8; j++) br[j] = Bs[k][tc*8 + j];
#pragma unroll
            for (int i = 0; i < 8; i++)
#pragma unroll
                for (int j = 0; j < 8; j++)
                    acc[i][j] = fmaf(ar[i], br[j], acc[i][j]);
        }
        __syncthreads();
    }
#pragma unroll
    for (int i = 0; i < 8; i++) {
        int m = blockIdx.y * 128 + tr*8 + i;
        if (m >= M) continue;
#pragma unroll
        for (int j = 0; j < 8; j++) {
            int n = blockIdx.x * 128 + tc*8 + j;
            if (n >= N) continue;
            float v = acc[i][j];
            if (bias) v += bias[n];
            if (act == 1) v = (v > 20.f) ? v : log1pf(expf(v));
            if (add) v += add[(long)m * ldadd + n];
            C[(long)m * ldc + n] = v;
        }
    }
}

// ---------------- causal depthwise conv (K=4) + SiLU ----------------
// reads x-branch half of xz (row stride 2*DI), writes xb
__global__ void conv_silu_k(const float* __restrict__ xz, const float* __restrict__ cw,
                            const float* __restrict__ cb, float* __restrict__ xb) {
    long idx = (long)blockIdx.x * 256 + threadIdx.x;   // < B*L*DI
    int d = idx & (DI_ - 1);
    long bl = idx >> 11;                 // b*L + l
    int l = (int)(bl & (L_ - 1));
    float acc = cb[d];
#pragma unroll
    for (int k = 0; k < K_; k++) {
        int lp = l + k - (K_ - 1);
        if (lp >= 0)
            acc = fmaf(cw[d*K_ + k], xz[(bl + (k - (K_-1))) * (2*DI_) + d], acc);
    }
    acc = acc / (1.f + expf(-acc));
    xb[idx] = acc;
}

// ---------------- selective SSM scan + D skip + z-gating ----------------
// 16 lanes per (b,d) channel (one per state n); 256 threads = 16 channels/block
__global__ void ssm_scan_k(const float* __restrict__ xb, const float* __restrict__ xp,
                           const float* __restrict__ dl, const float* __restrict__ xz,
                           const float* __restrict__ Alog, const float* __restrict__ Dp,
                           float* __restrict__ y) {
    int t = threadIdx.x;
    int g = t >> 4, lane = t & 15;
    int ch = blockIdx.x * 16 + g;
    int b = ch >> 11;          // / DI
    int d = ch & (DI_ - 1);
    float A = -expf(Alog[d*N_ + lane]);
    float Dv = Dp[d];
    float h = 0.f;
    long rowbase = (long)b * L_;
    for (int l = 0; l < L_; l++) {
        long r = rowbase + l;
        float dv = dl[r*DI_ + d];
        float xv = xb[r*DI_ + d];
        float Bv = xp[r*XPW_ + DTR_ + lane];
        float Cv = xp[r*XPW_ + DTR_ + N_ + lane];
        h = fmaf(expf(dv * A), h, dv * Bv * xv);
        float c = h * Cv;
        c += __shfl_xor_sync(~0u, c, 8);
        c += __shfl_xor_sync(~0u, c, 4);
        c += __shfl_xor_sync(~0u, c, 2);
        c += __shfl_xor_sync(~0u, c, 1);
        if (lane == 0) {
            float z = xz[r*(2*DI_) + DI_ + d];
            float yv = c + xv * Dv;
            y[r*DI_ + d] = yv * (z / (1.f + expf(-z)));
        }
    }
}

// ---------------- head: out[b,p] = fin[b,:] . head_w[p,:] ----------------
__global__ void head_k(const float* __restrict__ fin, const float* __restrict__ hw,
                       float* __restrict__ out) {
    int wid = blockIdx.x * 8 + (threadIdx.x >> 5);
    int lane = threadIdx.x & 31;
    if (wid >= B_ * P_) return;
    int b = wid / P_, p = wid % P_;
    const float* a = fin + (long)b * DM_;
    const float* w = hw + (long)p * DM_;
    float s = 0.f;
    for (int k = lane; k < DM_; k += 32) s = fmaf(a[k], w[k], s);
#pragma unroll
    for (int o = 16; o; o >>= 1) s += __shfl_xor_sync(~0u, s, o);
    if (lane == 0) out[wid] = s;
}

// ---------------- launch ----------------
extern "C" void kernel_launch(void* const* d_in, const int* in_sizes, int n_in,
                              void* d_out, int out_size) {
    const int*   tokens    = (const int*)  d_in[0];
    const float* tok_emb   = (const float*)d_in[1];
    const float* pos_emb   = (const float*)d_in[2];
    const float* ln_w      = (const float*)d_in[3];
    const float* ln_b      = (const float*)d_in[4];
    const float* in_proj_w = (const float*)d_in[5];
    const float* conv_w    = (const float*)d_in[6];
    const float* conv_b    = (const float*)d_in[7];
    const float* xproj_w   = (const float*)d_in[8];
    const float* dt_w      = (const float*)d_in[9];
    const float* dt_b      = (const float*)d_in[10];
    const float* A_log     = (const float*)d_in[11];
    const float* D_param   = (const float*)d_in[12];
    const float* out_proj_w= (const float*)d_in[13];
    const float* fnorm_w   = (const float*)d_in[14];
    const float* fnorm_b   = (const float*)d_in[15];
    const float* head_w    = (const float*)d_in[16];
    float* out = (float*)d_out;

    void *ph, *px, *pxz, *pxb, *pxp, *pdl, *py, *pfin;
    cudaGetSymbolAddress(&ph,  g_h);
    cudaGetSymbolAddress(&px,  g_x);
    cudaGetSymbolAddress(&pxz, g_xz);
    cudaGetSymbolAddress(&pxb, g_xb);
    cudaGetSymbolAddress(&pxp, g_xp);
    cudaGetSymbolAddress(&pdl, g_dl);
    cudaGetSymbolAddress(&py,  g_y);
    cudaGetSymbolAddress(&pfin,g_fin);
    float* h  = (float*)ph;   float* x  = (float*)px;
    float* xz = (float*)pxz;  float* xb = (float*)pxb;
    float* xp = (float*)pxp;  float* dl = (float*)pdl;
    float* y  = (float*)py;   float* fin= (float*)pfin;

    embed_k<<<M_TOK, 256>>>(tokens, tok_emb, pos_emb, h);

    for (int i = 0; i < NL_; i++) {
        // 1. layernorm
        ln_k<<<M_TOK, 256>>>(h, DM_, x, DM_, ln_w + i*DM_, ln_b + i*DM_);
        // 2. in_proj: xz = x @ ipw.T   (2048 x 4096 x 1024)
        sgemm_nt<<<dim3(32, 16), 256>>>(M_TOK, 2*DI_, DM_,
            x, DM_, in_proj_w + (long)i*2*DI_*DM_, DM_,
            xz, 2*DI_, nullptr, nullptr, 0, 0);
        // 3. causal conv + silu on x half
        conv_silu_k<<<(M_TOK*DI_)/256, 256>>>(xz, conv_w + (long)i*DI_*K_, conv_b + (long)i*DI_, xb);
        // 4. xproj: xp = xb @ xpw.T    (2048 x 160 x 2048)
        sgemm_nt<<<dim3(2, 16), 256>>>(M_TOK, XPW_, DI_,
            xb, DI_, xproj_w + (long)i*XPW_*DI_, DI_,
            xp, XPW_, nullptr, nullptr, 0, 0);
        // 5. delta = softplus(dt_r @ dtw.T + dtb)   (2048 x 2048 x 128), A = xp[:, :128]
        sgemm_nt<<<dim3(16, 16), 256>>>(M_TOK, DI_, DTR_,
            xp, XPW_, dt_w + (long)i*DI_*DTR_, DTR_,
            dl, DI_, dt_b + (long)i*DI_, nullptr, 0, 1);
        // 6. SSM scan + D skip + z gate
        ssm_scan_k<<<(B_*DI_)/16, 256>>>(xb, xp, dl, xz,
            A_log + (long)i*DI_*N_, D_param + (long)i*DI_, y);
        // 7. out_proj + residual: h = y @ opw.T + h  (2048 x 1024 x 2048)
        sgemm_nt<<<dim3(8, 16), 256>>>(M_TOK, DM_, DI_,
            y, DI_, out_proj_w + (long)i*DM_*DI_, DI_,
            h, DM_, nullptr, h, DM_, 0);
    }

    // final layernorm on last token of each batch row
    ln_k<<<B_, 256>>>(h + (long)(L_-1)*DM_, (long)L_*DM_, fin, DM_, fnorm_w, fnorm_b);
    // head
    head_k<<<P_, 256>>>(fin, head_w, out);
}

// round 3
// speedup vs baseline: 1.3644x; 1.3644x over previous
#include <cuda_runtime.h>
#include <math.h>

// Problem constants
#define B_  8
#define L_  256
#define DM_ 1024
#define DI_ 2048
#define N_  16
#define K_  4
#define NL_ 4
#define DTR_ 128
#define P_  97
#define M_TOK (B_*L_)          // 2048 token rows
#define XPW_ (DTR_ + 2*N_)     // 160

// GEMM tiling
#define BM 128
#define BN 128
#define BK 16
#define SST 132                // smem row stride in words ([k][m] layout)

// ---------------- scratch (static device globals; no allocation) ----------------
__device__ __align__(16) float g_h [M_TOK*DM_];
__device__ __align__(16) float g_x [M_TOK*DM_];
__device__ __align__(16) float g_xz[M_TOK*2*DI_];
__device__ __align__(16) float g_xb[M_TOK*DI_];
__device__ __align__(16) float g_xp[M_TOK*XPW_];
__device__ __align__(16) float g_dl[M_TOK*DI_];
__device__ __align__(16) float g_y [M_TOK*DI_];
__device__ __align__(16) float g_fin[B_*DM_];

// ---------------- embedding ----------------
__global__ void embed_k(const int* __restrict__ tok, const float* __restrict__ te,
                        const float* __restrict__ pe, float* __restrict__ h) {
    int row = blockIdx.x;
    int l = row & (L_ - 1);
    int t = tok[row];
    const float* tsrc = te + (long)t * DM_;
    const float* psrc = pe + (long)l * DM_;
    float* dst = h + (long)row * DM_;
    for (int d = threadIdx.x; d < DM_; d += 256)
        dst[d] = tsrc[d] + psrc[d];
}

// ---------------- layernorm ----------------
__global__ void ln_k(const float* __restrict__ in, long istride,
                     float* __restrict__ out, long ostride,
                     const float* __restrict__ w, const float* __restrict__ bb) {
    __shared__ float red[8];
    __shared__ float s_mean, s_rstd;
    int t = threadIdx.x;
    int row = blockIdx.x;
    const float* src = in + (long)row * istride;
    float v[4];
    float s = 0.f;
#pragma unroll
    for (int i = 0; i < 4; i++) { v[i] = src[t + i*256]; s += v[i]; }
#pragma unroll
    for (int o = 16; o; o >>= 1) s += __shfl_xor_sync(~0u, s, o);
    if ((t & 31) == 0) red[t >> 5] = s;
    __syncthreads();
    if (t < 32) {
        float x = (t < 8) ? red[t] : 0.f;
#pragma unroll
        for (int o = 4; o; o >>= 1) x += __shfl_xor_sync(~0u, x, o);
        if (t == 0) s_mean = x * (1.f/DM_);
    }
    __syncthreads();
    float mean = s_mean;
    float q = 0.f;
#pragma unroll
    for (int i = 0; i < 4; i++) { float d = v[i] - mean; q += d * d; }
#pragma unroll
    for (int o = 16; o; o >>= 1) q += __shfl_xor_sync(~0u, q, o);
    if ((t & 31) == 0) red[t >> 5] = q;
    __syncthreads();
    if (t < 32) {
        float x = (t < 8) ? red[t] : 0.f;
#pragma unroll
        for (int o = 4; o; o >>= 1) x += __shfl_xor_sync(~0u, x, o);
        if (t == 0) s_rstd = rsqrtf(x * (1.f/DM_) + 1e-5f);
    }
    __syncthreads();
    float r = s_rstd;
    float* dst = out + (long)row * ostride;
#pragma unroll
    for (int i = 0; i < 4; i++) {
        int idx = t + i*256;
        dst[idx] = (v[i] - mean) * r * w[idx] + bb[idx];
    }
}

// ---------------- tf32 helpers ----------------
__device__ __forceinline__ unsigned f2tf(float f) {
    unsigned r;
    asm("cvt.rna.tf32.f32 %0, %1;" : "=r"(r) : "f"(f));
    return r;
}

// hi = tf32(f); lo = tf32(f - hi)  (f - hi is exact in fp32)
__device__ __forceinline__ void split_tf32(float f, unsigned& hi, unsigned& lo) {
    unsigned h = f2tf(f);
    hi = h;
    lo = f2tf(f - __uint_as_float(h));
}

__device__ __forceinline__ void mma_tf32(float* c, const unsigned* a, const unsigned* b) {
    asm volatile(
        "mma.sync.aligned.m16n8k8.row.col.f32.tf32.tf32.f32 "
        "{%0,%1,%2,%3}, {%4,%5,%6,%7}, {%8,%9}, {%0,%1,%2,%3};"
        : "+f"(c[0]), "+f"(c[1]), "+f"(c[2]), "+f"(c[3])
        : "r"(a[0]), "r"(a[1]), "r"(a[2]), "r"(a[3]), "r"(b[0]), "r"(b[1]));
}

// ---------------- 3xTF32 tensor-core GEMM: C[m,n] = sum_k A[m,k]*W[n,k] ----------------
// 128x128x16 tiles, 256 threads (8 warps, 2x4 warp grid, 64x32 warp tile).
// Error-compensated: A = Ah+Al, B = Bh+Bl; acc += Ah*Bh + Ah*Bl + Al*Bh.
// act: 0=none, 1=softplus. bias added per-n, add accumulates per-element.
__global__ __launch_bounds__(256, 2)
void gemm_3xtf32(int M, int N, int Kd,
                 const float* __restrict__ A, int lda,
                 const float* __restrict__ W, int ldb,
                 float* __restrict__ C, int ldc,
                 const float* __restrict__ bias,
                 const float* __restrict__ add, int ldadd,
                 int act) {
    __shared__ unsigned Ah[BK*SST], Al[BK*SST];
    __shared__ unsigned Bh[BK*SST], Bl[BK*SST];
    int tid = threadIdx.x;
    int lane = tid & 31, wid = tid >> 5;
    int warpM = (wid >> 2) * 64;      // 0 or 64
    int warpN = (wid & 3) * 32;       // 0,32,64,96
    int grp = lane >> 2, thr4 = lane & 3;

    // global load mapping: each thread loads 2 float4 per matrix per stage
    int r0 = tid >> 2;                // 0..63
    int c4 = (tid & 3) * 4;           // 0,4,8,12
    int gAr0 = blockIdx.y * BM + r0, gAr1 = gAr0 + 64;
    int gBr0 = blockIdx.x * BN + r0, gBr1 = gBr0 + 64;
    bool aOK0 = gAr0 < M, aOK1 = gAr1 < M;
    bool bOK0 = gBr0 < N, bOK1 = gBr1 < N;
    const float* Ap0 = A + (long)gAr0 * lda + c4;
    const float* Ap1 = A + (long)gAr1 * lda + c4;
    const float* Wp0 = W + (long)gBr0 * ldb + c4;
    const float* Wp1 = W + (long)gBr1 * ldb + c4;

    float acc[4][4][4];
#pragma unroll
    for (int i = 0; i < 4; i++)
#pragma unroll
        for (int j = 0; j < 4; j++)
#pragma unroll
            for (int q = 0; q < 4; q++) acc[i][j][q] = 0.f;

    const float4 z4 = make_float4(0,0,0,0);
    float4 av0, av1, bv0, bv1;

    // preload stage 0 into regs
    av0 = aOK0 ? *(const float4*)(Ap0) : z4;
    av1 = aOK1 ? *(const float4*)(Ap1) : z4;
    bv0 = bOK0 ? *(const float4*)(Wp0) : z4;
    bv1 = bOK1 ? *(const float4*)(Wp1) : z4;

    int nst = Kd / BK;
    for (int kt = 0; kt < nst; kt++) {
        // deposit regs -> smem (hi/lo split)
        {
            unsigned h, l;
            split_tf32(av0.x, h, l); Ah[(c4+0)*SST + r0] = h; Al[(c4+0)*SST + r0] = l;
            split_tf32(av0.y, h, l); Ah[(c4+1)*SST + r0] = h; Al[(c4+1)*SST + r0] = l;
            split_tf32(av0.z, h, l); Ah[(c4+2)*SST + r0] = h; Al[(c4+2)*SST + r0] = l;
            split_tf32(av0.w, h, l); Ah[(c4+3)*SST + r0] = h; Al[(c4+3)*SST + r0] = l;
            split_tf32(av1.x, h, l); Ah[(c4+0)*SST + r0+64] = h; Al[(c4+0)*SST + r0+64] = l;
            split_tf32(av1.y, h, l); Ah[(c4+1)*SST + r0+64] = h; Al[(c4+1)*SST + r0+64] = l;
            split_tf32(av1.z, h, l); Ah[(c4+2)*SST + r0+64] = h; Al[(c4+2)*SST + r0+64] = l;
            split_tf32(av1.w, h, l); Ah[(c4+3)*SST + r0+64] = h; Al[(c4+3)*SST + r0+64] = l;
            split_tf32(bv0.x, h, l); Bh[(c4+0)*SST + r0] = h; Bl[(c4+0)*SST + r0] = l;
            split_tf32(bv0.y, h, l); Bh[(c4+1)*SST + r0] = h; Bl[(c4+1)*SST + r0] = l;
            split_tf32(bv0.z, h, l); Bh[(c4+2)*SST + r0] = h; Bl[(c4+2)*SST + r0] = l;
            split_tf32(bv0.w, h, l); Bh[(c4+3)*SST + r0] = h; Bl[(c4+3)*SST + r0] = l;
            split_tf32(bv1.x, h, l); Bh[(c4+0)*SST + r0+64] = h; Bl[(c4+0)*SST + r0+64] = l;
            split_tf32(bv1.y, h, l); Bh[(c4+1)*SST + r0+64] = h; Bl[(c4+1)*SST + r0+64] = l;
            split_tf32(bv1.z, h, l); Bh[(c4+2)*SST + r0+64] = h; Bl[(c4+2)*SST + r0+64] = l;
            split_tf32(bv1.w, h, l); Bh[(c4+3)*SST + r0+64] = h; Bl[(c4+3)*SST + r0+64] = l;
        }
        __syncthreads();

        // prefetch next stage into regs (latency overlapped with compute below)
        if (kt + 1 < nst) {
            int k0 = (kt + 1) * BK;
            av0 = aOK0 ? *(const float4*)(Ap0 + k0) : z4;
            av1 = aOK1 ? *(const float4*)(Ap1 + k0) : z4;
            bv0 = bOK0 ? *(const float4*)(Wp0 + k0) : z4;
            bv1 = bOK1 ? *(const float4*)(Wp1 + k0) : z4;
        }

        // compute
#pragma unroll
        for (int ks = 0; ks < 2; ks++) {
            int krow = ks*8 + thr4;
            unsigned bh[4][2], bl[4][2];
#pragma unroll
            for (int j = 0; j < 4; j++) {
                int n = warpN + j*8 + grp;
                bh[j][0] = Bh[krow*SST + n];
                bh[j][1] = Bh[(krow+4)*SST + n];
                bl[j][0] = Bl[krow*SST + n];
                bl[j][1] = Bl[(krow+4)*SST + n];
            }
#pragma unroll
            for (int i = 0; i < 4; i++) {
                int m = warpM + i*16 + grp;
                unsigned ah[4], al[4];
                ah[0] = Ah[krow*SST + m];     ah[1] = Ah[krow*SST + m + 8];
                ah[2] = Ah[(krow+4)*SST + m]; ah[3] = Ah[(krow+4)*SST + m + 8];
                al[0] = Al[krow*SST + m];     al[1] = Al[krow*SST + m + 8];
                al[2] = Al[(krow+4)*SST + m]; al[3] = Al[(krow+4)*SST + m + 8];
#pragma unroll
                for (int j = 0; j < 4; j++) {
                    mma_tf32(acc[i][j], ah, bh[j]);   // hi*hi
                    mma_tf32(acc[i][j], ah, bl[j]);   // hi*lo
                    mma_tf32(acc[i][j], al, bh[j]);   // lo*hi
                }
            }
        }
        __syncthreads();
    }

    // epilogue
#pragma unroll
    for (int i = 0; i < 4; i++) {
        int gm0 = blockIdx.y * BM + warpM + i*16 + grp;
#pragma unroll
        for (int j = 0; j < 4; j++) {
            int gn = blockIdx.x * BN + warpN + j*8 + 2*thr4;
#pragma unroll
            for (int half = 0; half < 2; half++) {
                int gm = gm0 + half*8;
                if (gm >= M) continue;
#pragma unroll
                for (int q = 0; q < 2; q++) {
                    int n = gn + q;
                    if (n >= N) continue;
                    float v = acc[i][j][half*2 + q];
                    if (bias) v += bias[n];
                    if (act == 1) v = (v > 20.f) ? v : log1pf(expf(v));
                    if (add) v += add[(long)gm * ldadd + n];
                    C[(long)gm * ldc + n] = v;
                }
            }
        }
    }
}

// ---------------- causal depthwise conv (K=4) + SiLU ----------------
__global__ void conv_silu_k(const float* __restrict__ xz, const float* __restrict__ cw,
                            const float* __restrict__ cb, float* __restrict__ xb) {
    long idx = (long)blockIdx.x * 256 + threadIdx.x;
    int d = idx & (DI_ - 1);
    long bl = idx >> 11;
    int l = (int)(bl & (L_ - 1));
    float acc = cb[d];
#pragma unroll
    for (int k = 0; k < K_; k++) {
        int lp = l + k - (K_ - 1);
        if (lp >= 0)
            acc = fmaf(cw[d*K_ + k], xz[(bl + (k - (K_-1))) * (2*DI_) + d], acc);
    }
    acc = acc / (1.f + expf(-acc));
    xb[idx] = acc;
}

// ---------------- selective SSM scan + D skip + z-gating ----------------
__global__ void ssm_scan_k(const float* __restrict__ xb, const float* __restrict__ xp,
                           const float* __restrict__ dl, const float* __restrict__ xz,
                           const float* __restrict__ Alog, const float* __restrict__ Dp,
                           float* __restrict__ y) {
    int t = threadIdx.x;
    int g = t >> 4, lane = t & 15;
    int ch = blockIdx.x * 16 + g;
    int b = ch >> 11;
    int d = ch & (DI_ - 1);
    float A = -expf(Alog[d*N_ + lane]);
    float Dv = Dp[d];
    float h = 0.f;
    long rowbase = (long)b * L_;
    for (int l = 0; l < L_; l++) {
        long r = rowbase + l;
        float dv = dl[r*DI_ + d];
        float xv = xb[r*DI_ + d];
        float Bv = xp[r*XPW_ + DTR_ + lane];
        float Cv = xp[r*XPW_ + DTR_ + N_ + lane];
        h = fmaf(expf(dv * A), h, dv * Bv * xv);
        float c = h * Cv;
        c += __shfl_xor_sync(~0u, c, 8);
        c += __shfl_xor_sync(~0u, c, 4);
        c += __shfl_xor_sync(~0u, c, 2);
        c += __shfl_xor_sync(~0u, c, 1);
        if (lane == 0) {
            float z = xz[r*(2*DI_) + DI_ + d];
            float yv = c + xv * Dv;
            y[r*DI_ + d] = yv * (z / (1.f + expf(-z)));
        }
    }
}

// ---------------- head ----------------
__global__ void head_k(const float* __restrict__ fin, const float* __restrict__ hw,
                       float* __restrict__ out) {
    int wid = blockIdx.x * 8 + (threadIdx.x >> 5);
    int lane = threadIdx.x & 31;
    if (wid >= B_ * P_) return;
    int b = wid / P_, p = wid % P_;
    const float* a = fin + (long)b * DM_;
    const float* w = hw + (long)p * DM_;
    float s = 0.f;
    for (int k = lane; k < DM_; k += 32) s = fmaf(a[k], w[k], s);
#pragma unroll
    for (int o = 16; o; o >>= 1) s += __shfl_xor_sync(~0u, s, o);
    if (lane == 0) out[wid] = s;
}

// ---------------- launch ----------------
extern "C" void kernel_launch(void* const* d_in, const int* in_sizes, int n_in,
                              void* d_out, int out_size) {
    const int*   tokens    = (const int*)  d_in[0];
    const float* tok_emb   = (const float*)d_in[1];
    const float* pos_emb   = (const float*)d_in[2];
    const float* ln_w      = (const float*)d_in[3];
    const float* ln_b      = (const float*)d_in[4];
    const float* in_proj_w = (const float*)d_in[5];
    const float* conv_w    = (const float*)d_in[6];
    const float* conv_b    = (const float*)d_in[7];
    const float* xproj_w   = (const float*)d_in[8];
    const float* dt_w      = (const float*)d_in[9];
    const float* dt_b      = (const float*)d_in[10];
    const float* A_log     = (const float*)d_in[11];
    const float* D_param   = (const float*)d_in[12];
    const float* out_proj_w= (const float*)d_in[13];
    const float* fnorm_w   = (const float*)d_in[14];
    const float* fnorm_b   = (const float*)d_in[15];
    const float* head_w    = (const float*)d_in[16];
    float* out = (float*)d_out;

    void *ph, *px, *pxz, *pxb, *pxp, *pdl, *py, *pfin;
    cudaGetSymbolAddress(&ph,  g_h);
    cudaGetSymbolAddress(&px,  g_x);
    cudaGetSymbolAddress(&pxz, g_xz);
    cudaGetSymbolAddress(&pxb, g_xb);
    cudaGetSymbolAddress(&pxp, g_xp);
    cudaGetSymbolAddress(&pdl, g_dl);
    cudaGetSymbolAddress(&py,  g_y);
    cudaGetSymbolAddress(&pfin,g_fin);
    float* h  = (float*)ph;   float* x  = (float*)px;
    float* xz = (float*)pxz;  float* xb = (float*)pxb;
    float* xp = (float*)pxp;  float* dl = (float*)pdl;
    float* y  = (float*)py;   float* fin= (float*)pfin;

    embed_k<<<M_TOK, 256>>>(tokens, tok_emb, pos_emb, h);

    for (int i = 0; i < NL_; i++) {
        ln_k<<<M_TOK, 256>>>(h, DM_, x, DM_, ln_w + i*DM_, ln_b + i*DM_);
        // in_proj: 2048 x 4096 x 1024
        gemm_3xtf32<<<dim3(32, 16), 256>>>(M_TOK, 2*DI_, DM_,
            x, DM_, in_proj_w + (long)i*2*DI_*DM_, DM_,
            xz, 2*DI_, nullptr, nullptr, 0, 0);
        conv_silu_k<<<(M_TOK*DI_)/256, 256>>>(xz, conv_w + (long)i*DI_*K_, conv_b + (long)i*DI_, xb);
        // xproj: 2048 x 160 x 2048
        gemm_3xtf32<<<dim3(2, 16), 256>>>(M_TOK, XPW_, DI_,
            xb, DI_, xproj_w + (long)i*XPW_*DI_, DI_,
            xp, XPW_, nullptr, nullptr, 0, 0);
        // delta = softplus(dt_r @ dtw.T + dtb): 2048 x 2048 x 128
        gemm_3xtf32<<<dim3(16, 16), 256>>>(M_TOK, DI_, DTR_,
            xp, XPW_, dt_w + (long)i*DI_*DTR_, DTR_,
            dl, DI_, dt_b + (long)i*DI_, nullptr, 0, 1);
        ssm_scan_k<<<(B_*DI_)/16, 256>>>(xb, xp, dl, xz,
            A_log + (long)i*DI_*N_, D_param + (long)i*DI_, y);
        // out_proj + residual: 2048 x 1024 x 2048
        gemm_3xtf32<<<dim3(8, 16), 256>>>(M_TOK, DM_, DI_,
            y, DI_, out_proj_w + (long)i*DM_*DI_, DI_,
            h, DM_, nullptr, h, DM_, 0);
    }

    ln_k<<<B_, 256>>>(h + (long)(L_-1)*DM_, (long)L_*DM_, fin, DM_, fnorm_w, fnorm_b);
    head_k<<<P_, 256>>>(fin, head_w, out);
}